// round 4
// baseline (speedup 1.0000x reference)
#include <cuda_runtime.h>

// Problem dims (fixed per reference)
#define B_DIM 16
#define T_DIM 2048
#define D_DIM 1024
#define C_DIM 512
#define M_DIM (B_DIM * T_DIM)          // 32768 rows for CAM GEMM

// Output layout: [soft | raw | logits | loss]
#define SOFT_OFF   ((size_t)0)
#define RAW_OFF    ((size_t)M_DIM * C_DIM)                    // 16,777,216
#define LOGITS_OFF ((size_t)2 * M_DIM * C_DIM)                // 33,554,432
#define LOSS_OFF   (LOGITS_OFF + (size_t)B_DIM * C_DIM)       // 33,562,624

// Scratch (static __device__, no allocation)
__device__ float g_cam[(size_t)M_DIM * C_DIM];   // 64 MB
__device__ float g_pooled[B_DIM * D_DIM];        // 64 KB (sum over T; divided later)

// ---------------------------------------------------------------------------
// CAM GEMM: C[m][n] = sum_k A[m][k] * W[n][k]
// A = features [M, D], W = [C, D] row-major. Classic 128x128x8 tile,
// 256 threads, 8x8 register micro-tile.
// ---------------------------------------------------------------------------
#define BM 128
#define BN 128
#define BK 8
#define TM 8
#define TN 8

__global__ void __launch_bounds__(256)
cam_gemm_kernel(const float* __restrict__ A, const float* __restrict__ W,
                float* __restrict__ Cout)
{
    __shared__ float As[BK][BM];
    __shared__ float Bs[BK][BN];

    const int tid = threadIdx.x;
    const int m0 = blockIdx.y * BM;
    const int n0 = blockIdx.x * BN;

    const int lrow  = tid >> 1;        // 0..127
    const int lquad = (tid & 1) * 4;   // 0 or 4

    const float* Aptr = A + (size_t)(m0 + lrow) * D_DIM + lquad;
    const float* Wptr = W + (size_t)(n0 + lrow) * D_DIM + lquad;

    const int ty = tid >> 4;   // 0..15
    const int tx = tid & 15;   // 0..15

    float acc[TM][TN];
    #pragma unroll
    for (int i = 0; i < TM; i++)
        #pragma unroll
        for (int j = 0; j < TN; j++)
            acc[i][j] = 0.0f;

    for (int k0 = 0; k0 < D_DIM; k0 += BK) {
        // global loads (issued before the barrier for latency overlap)
        float4 av = *(const float4*)(Aptr + k0);
        float4 bv = *(const float4*)(Wptr + k0);

        __syncthreads();   // previous iteration's reads done
        As[lquad + 0][lrow] = av.x;
        As[lquad + 1][lrow] = av.y;
        As[lquad + 2][lrow] = av.z;
        As[lquad + 3][lrow] = av.w;
        Bs[lquad + 0][lrow] = bv.x;
        Bs[lquad + 1][lrow] = bv.y;
        Bs[lquad + 2][lrow] = bv.z;
        Bs[lquad + 3][lrow] = bv.w;
        __syncthreads();

        #pragma unroll
        for (int k = 0; k < BK; k++) {
            float af[TM], bf[TN];
            *(float4*)(af + 0) = *(const float4*)&As[k][ty * TM + 0];
            *(float4*)(af + 4) = *(const float4*)&As[k][ty * TM + 4];
            *(float4*)(bf + 0) = *(const float4*)&Bs[k][tx * TN + 0];
            *(float4*)(bf + 4) = *(const float4*)&Bs[k][tx * TN + 4];
            #pragma unroll
            for (int i = 0; i < TM; i++)
                #pragma unroll
                for (int j = 0; j < TN; j++)
                    acc[i][j] = fmaf(af[i], bf[j], acc[i][j]);
        }
    }

    float* cp = Cout + (size_t)(m0 + ty * TM) * C_DIM + n0 + tx * TN;
    #pragma unroll
    for (int i = 0; i < TM; i++) {
        *(float4*)(cp + (size_t)i * C_DIM + 0) =
            make_float4(acc[i][0], acc[i][1], acc[i][2], acc[i][3]);
        *(float4*)(cp + (size_t)i * C_DIM + 4) =
            make_float4(acc[i][4], acc[i][5], acc[i][6], acc[i][7]);
    }
}

// ---------------------------------------------------------------------------
// Row softmax over C=512; write result to both soft and raw output regions.
// One block (128 threads) per row; each thread owns one float4.
// ---------------------------------------------------------------------------
__global__ void __launch_bounds__(128)
softmax_kernel(const float* __restrict__ cam, float* __restrict__ out)
{
    const int row  = blockIdx.x;
    const int tid  = threadIdx.x;
    const int lane = tid & 31;
    const int wid  = tid >> 5;

    const float4* rp = (const float4*)(cam + (size_t)row * C_DIM);
    float4 v = rp[tid];

    __shared__ float red[8];

    // max
    float m = fmaxf(fmaxf(v.x, v.y), fmaxf(v.z, v.w));
    #pragma unroll
    for (int o = 16; o > 0; o >>= 1)
        m = fmaxf(m, __shfl_xor_sync(0xFFFFFFFFu, m, o));
    if (lane == 0) red[wid] = m;
    __syncthreads();
    m = fmaxf(fmaxf(red[0], red[1]), fmaxf(red[2], red[3]));

    // exp + sum
    float e0 = expf(v.x - m), e1 = expf(v.y - m);
    float e2 = expf(v.z - m), e3 = expf(v.w - m);
    float s = (e0 + e1) + (e2 + e3);
    #pragma unroll
    for (int o = 16; o > 0; o >>= 1)
        s += __shfl_xor_sync(0xFFFFFFFFu, s, o);
    if (lane == 0) red[4 + wid] = s;
    __syncthreads();
    s = (red[4] + red[5]) + (red[6] + red[7]);

    float inv = 1.0f / s;
    float4 o4 = make_float4(e0 * inv, e1 * inv, e2 * inv, e3 * inv);

    ((float4*)(out + SOFT_OFF + (size_t)row * C_DIM))[tid] = o4;
    ((float4*)(out + RAW_OFF  + (size_t)row * C_DIM))[tid] = o4;
}

// ---------------------------------------------------------------------------
// Mean pooling: g_pooled[b][d] = sum_t features[b][t][d]  (sum; /T at use)
// ---------------------------------------------------------------------------
__global__ void zero_pooled_kernel()
{
    int i = blockIdx.x * blockDim.x + threadIdx.x;
    if (i < B_DIM * D_DIM) g_pooled[i] = 0.0f;
}

#define TSPLIT 8
__global__ void __launch_bounds__(256)
pooled_kernel(const float* __restrict__ f)
{
    const int d  = blockIdx.x * 256 + threadIdx.x;
    const int b  = blockIdx.z;
    const int t0 = blockIdx.y * (T_DIM / TSPLIT);
    const float* p = f + ((size_t)b * T_DIM + t0) * D_DIM + d;
    float s = 0.0f;
    #pragma unroll 4
    for (int t = 0; t < T_DIM / TSPLIT; t++)
        s += p[(size_t)t * D_DIM];
    atomicAdd(&g_pooled[b * D_DIM + d], s);
}

// ---------------------------------------------------------------------------
// logits[b][c] = dot(pooled[b], W[c]) / T + bias[c]; one warp per (b,c)
// ---------------------------------------------------------------------------
__global__ void __launch_bounds__(256)
logits_kernel(const float* __restrict__ W, const float* __restrict__ bias,
              float* __restrict__ out)
{
    const int b    = blockIdx.x;
    const int c    = blockIdx.y * 8 + (threadIdx.x >> 5);
    const int lane = threadIdx.x & 31;

    const float4* wp = (const float4*)(W + (size_t)c * D_DIM);
    const float4* pp = (const float4*)(g_pooled + b * D_DIM);

    float s = 0.0f;
    #pragma unroll
    for (int i = lane; i < D_DIM / 4; i += 32) {
        float4 w = wp[i];
        float4 p = pp[i];
        s += w.x * p.x + w.y * p.y + w.z * p.z + w.w * p.w;
    }
    #pragma unroll
    for (int o = 16; o > 0; o >>= 1)
        s += __shfl_xor_sync(0xFFFFFFFFu, s, o);

    if (lane == 0)
        out[LOGITS_OFF + (size_t)b * C_DIM + c] = s * (1.0f / T_DIM) + bias[c];
}

// ---------------------------------------------------------------------------
// loss = mean_b( -(logits[b][label_b] - logsumexp(logits[b])) )
// One warp per batch row, single block.
// NOTE: labels are int32 on device — JAX runs with x64 disabled, so
// jax.random.randint(dtype=int64) silently yields int32. Reading int64 here
// was the round-2 bug (paired-up labels -> wrong CE indices).
// ---------------------------------------------------------------------------
__global__ void __launch_bounds__(512)
loss_kernel(const float* __restrict__ out_logits,
            const int* __restrict__ labels, float* __restrict__ out)
{
    const int w    = threadIdx.x >> 5;   // 0..15 -> b
    const int lane = threadIdx.x & 31;
    const float* lp = out_logits + (size_t)w * C_DIM;

    float m = -3.4e38f;
    for (int i = lane; i < C_DIM; i += 32) m = fmaxf(m, lp[i]);
    #pragma unroll
    for (int o = 16; o > 0; o >>= 1)
        m = fmaxf(m, __shfl_xor_sync(0xFFFFFFFFu, m, o));

    float s = 0.0f;
    for (int i = lane; i < C_DIM; i += 32) s += expf(lp[i] - m);
    #pragma unroll
    for (int o = 16; o > 0; o >>= 1)
        s += __shfl_xor_sync(0xFFFFFFFFu, s, o);

    __shared__ float lb[16];
    if (lane == 0) {
        int lab = labels[w];
        lb[w] = -(lp[lab] - m - logf(s));
    }
    __syncthreads();
    if (threadIdx.x == 0) {
        float t = 0.0f;
        #pragma unroll
        for (int i = 0; i < 16; i++) t += lb[i];
        out[LOSS_OFF] = t * (1.0f / B_DIM);
    }
}

// ---------------------------------------------------------------------------
extern "C" void kernel_launch(void* const* d_in, const int* in_sizes, int n_in,
                              void* d_out, int out_size)
{
    const float* features = (const float*)d_in[0];
    const int*   labels   = (const int*)d_in[1];
    const float* W        = (const float*)d_in[2];
    const float* bias     = (const float*)d_in[3];
    float*       out      = (float*)d_out;

    float* cam_ptr;
    cudaGetSymbolAddress((void**)&cam_ptr, g_cam);

    // 1) mean pool (sum into scratch)
    zero_pooled_kernel<<<(B_DIM * D_DIM + 255) / 256, 256>>>();
    pooled_kernel<<<dim3(D_DIM / 256, TSPLIT, B_DIM), 256>>>(features);

    // 2) CAM GEMM into scratch
    cam_gemm_kernel<<<dim3(C_DIM / BN, M_DIM / BM), 256>>>(features, W, cam_ptr);

    // 3) softmax -> soft + raw output regions
    softmax_kernel<<<M_DIM, 128>>>(cam_ptr, out);

    // 4) logits
    logits_kernel<<<dim3(B_DIM, C_DIM / 8), 256>>>(W, bias, out);

    // 5) loss (reads logits region of d_out)
    loss_kernel<<<1, 512>>>(out + LOGITS_OFF, labels, out);
}

// round 6
// speedup vs baseline: 2.2065x; 2.2065x over previous
#include <cuda_runtime.h>
#include <cuda_bf16.h>
#include <cstdint>

// Problem dims (fixed per reference)
#define B_DIM 16
#define T_DIM 2048
#define D_DIM 1024
#define C_DIM 512
#define M_DIM (B_DIM * T_DIM)          // 32768 rows for CAM GEMM
#define KBIG  (2 * D_DIM)              // 2048 stored: [hi | lo]
#define KVIRT (3 * D_DIM)              // 3072 virtual: hi*hi + hi*lo + lo*hi

// Output layout: [soft | raw | logits | loss]
#define SOFT_OFF   ((size_t)0)
#define RAW_OFF    ((size_t)M_DIM * C_DIM)
#define LOGITS_OFF ((size_t)2 * M_DIM * C_DIM)
#define LOSS_OFF   (LOGITS_OFF + (size_t)B_DIM * C_DIM)

// Scratch (static __device__, no allocation)
__device__ float          g_cam[(size_t)M_DIM * C_DIM];        // 64 MB
__device__ float          g_pooled[B_DIM * D_DIM];             // sums over T
__device__ __nv_bfloat16  g_Abig[(size_t)M_DIM * KBIG];        // 128 MB  [hi|lo]
__device__ __nv_bfloat16  g_Wbig[(size_t)C_DIM * KBIG];        // 2 MB    [hi|lo]

// ---------------------------------------------------------------------------
// PTX helpers
// ---------------------------------------------------------------------------
__device__ __forceinline__ void cpa16(uint32_t daddr, const void* gaddr) {
    asm volatile("cp.async.cg.shared.global [%0], [%1], 16;\n"
                 :: "r"(daddr), "l"(gaddr));
}
__device__ __forceinline__ void ldsm4(uint32_t& r0, uint32_t& r1,
                                      uint32_t& r2, uint32_t& r3, uint32_t addr) {
    asm volatile("ldmatrix.sync.aligned.m8n8.x4.shared.b16 {%0,%1,%2,%3}, [%4];"
                 : "=r"(r0), "=r"(r1), "=r"(r2), "=r"(r3) : "r"(addr));
}
__device__ __forceinline__ void mma16816(float* c, const uint32_t* a, const uint32_t* b) {
    asm volatile(
        "mma.sync.aligned.m16n8k16.row.col.f32.bf16.bf16.f32 "
        "{%0,%1,%2,%3}, {%4,%5,%6,%7}, {%8,%9}, {%0,%1,%2,%3};"
        : "+f"(c[0]), "+f"(c[1]), "+f"(c[2]), "+f"(c[3])
        : "r"(a[0]), "r"(a[1]), "r"(a[2]), "r"(a[3]), "r"(b[0]), "r"(b[1]));
}

// ---------------------------------------------------------------------------
// Fused conversion (fp32 -> bf16 hi/lo split) + mean-pool partial sums.
// ---------------------------------------------------------------------------
#define TSPLIT 8
__global__ void __launch_bounds__(256)
convert_pool_kernel(const float* __restrict__ f)
{
    const int d  = blockIdx.x * 256 + threadIdx.x;
    const int b  = blockIdx.z;
    const int t0 = blockIdx.y * (T_DIM / TSPLIT);

    float s = 0.0f;
    #pragma unroll 4
    for (int t = 0; t < T_DIM / TSPLIT; t++) {
        const size_t row = (size_t)b * T_DIM + t0 + t;
        float v = f[row * D_DIM + d];
        s += v;
        __nv_bfloat16 hi = __float2bfloat16(v);
        float lo = v - __bfloat162float(hi);
        g_Abig[row * KBIG + d]          = hi;
        g_Abig[row * KBIG + D_DIM + d]  = __float2bfloat16(lo);
    }
    atomicAdd(&g_pooled[b * D_DIM + d], s);
}

__global__ void __launch_bounds__(256)
convert_w_kernel(const float* __restrict__ W)
{
    const int i = blockIdx.x * 256 + threadIdx.x;   // < C*D
    const int c = i >> 10;
    const int d = i & (D_DIM - 1);
    float v = W[i];
    __nv_bfloat16 hi = __float2bfloat16(v);
    g_Wbig[(size_t)c * KBIG + d]         = hi;
    g_Wbig[(size_t)c * KBIG + D_DIM + d] = __float2bfloat16(v - __bfloat162float(hi));
}

__global__ void zero_pooled_kernel()
{
    int i = blockIdx.x * blockDim.x + threadIdx.x;
    if (i < B_DIM * D_DIM) g_pooled[i] = 0.0f;
}

// ---------------------------------------------------------------------------
// Tensor-core CAM GEMM over VIRTUAL K = 3072:
//   phase 0 (vk 0..1023):    A-hi * W-hi
//   phase 1 (vk 1024..2047): A-hi * W-lo
//   phase 2 (vk 2048..3071): A-lo * W-hi
// Sum = (a-eps_a)(w-eps_w) - lo_a*lo_w : error ~2^-16 relative.
// 128x128 CTA tile, BK=32, double-buffered cp.async, ldmatrix + HMMA.
// ---------------------------------------------------------------------------
#define STAGE_BYTES 8192                 // 128 rows * 64 B

__device__ __forceinline__ void gemm_issue_loads(
    const __nv_bfloat16* __restrict__ A, const __nv_bfloat16* __restrict__ Bw,
    int m0, int n0, int vk0, uint32_t baseA, uint32_t baseB, int stage,
    int ldrow, int ldc)
{
    const int kv    = vk0 & (D_DIM - 1);
    const int phase = vk0 >> 10;                       // 0,1,2
    const int kA = (phase == 2) ? (D_DIM + kv) : kv;   // lo only in phase 2
    const int kW = (phase == 1) ? (D_DIM + kv) : kv;   // lo only in phase 1

    #pragma unroll
    for (int j = 0; j < 2; j++) {
        const int row = ldrow + j * 64;
        const int sw  = ldc ^ ((row >> 1) & 3);
        cpa16(baseA + stage * STAGE_BYTES + row * 64 + sw * 16,
              A + (size_t)(m0 + row) * KBIG + kA + ldc * 8);
        cpa16(baseB + stage * STAGE_BYTES + row * 64 + sw * 16,
              Bw + (size_t)(n0 + row) * KBIG + kW + ldc * 8);
    }
}

__global__ void __launch_bounds__(256, 2)
cam_mma_kernel(const __nv_bfloat16* __restrict__ A,
               const __nv_bfloat16* __restrict__ Bw,
               float* __restrict__ Cout)
{
    __shared__ __align__(16) unsigned char sA[2 * STAGE_BYTES];
    __shared__ __align__(16) unsigned char sB[2 * STAGE_BYTES];

    const int tid    = threadIdx.x;
    const int lane   = tid & 31;
    const int wid    = tid >> 5;
    const int warp_m = wid >> 2;       // 0..1
    const int warp_n = wid & 3;        // 0..3
    const int m0 = blockIdx.y * 128;
    const int n0 = blockIdx.x * 128;

    const uint32_t baseA = (uint32_t)__cvta_generic_to_shared(sA);
    const uint32_t baseB = (uint32_t)__cvta_generic_to_shared(sB);

    const int ldrow = tid >> 2;        // 0..63 (j adds 64)
    const int ldc   = tid & 3;         // 16B chunk in row

    float acc[4][4][4];
    #pragma unroll
    for (int mt = 0; mt < 4; mt++)
        #pragma unroll
        for (int nt = 0; nt < 4; nt++)
            #pragma unroll
            for (int r = 0; r < 4; r++)
                acc[mt][nt][r] = 0.0f;

    gemm_issue_loads(A, Bw, m0, n0, 0, baseA, baseB, 0, ldrow, ldc);
    asm volatile("cp.async.commit_group;\n");

    const int NITER = KVIRT / 32;      // 96
    for (int it = 0; it < NITER; it++) {
        if (it + 1 < NITER)
            gemm_issue_loads(A, Bw, m0, n0, (it + 1) * 32, baseA, baseB,
                             (it + 1) & 1, ldrow, ldc);
        asm volatile("cp.async.commit_group;\n");
        asm volatile("cp.async.wait_group 1;\n");
        __syncthreads();

        const int st = it & 1;
        #pragma unroll
        for (int ks = 0; ks < 2; ks++) {
            uint32_t afr[4][4];
            #pragma unroll
            for (int mt = 0; mt < 4; mt++) {
                const int row   = warp_m * 64 + mt * 16 + (lane & 15);
                const int chunk = (2 * ks + (lane >> 4)) ^ ((row >> 1) & 3);
                ldsm4(afr[mt][0], afr[mt][1], afr[mt][2], afr[mt][3],
                      baseA + st * STAGE_BYTES + row * 64 + chunk * 16);
            }
            uint32_t bfr[4][2];
            #pragma unroll
            for (int nt16 = 0; nt16 < 2; nt16++) {
                const int row   = warp_n * 32 + nt16 * 16 + (lane & 15);
                const int chunk = (2 * ks + (lane >> 4)) ^ ((row >> 1) & 3);
                uint32_t r0, r1, r2, r3;
                ldsm4(r0, r1, r2, r3,
                      baseB + st * STAGE_BYTES + row * 64 + chunk * 16);
                bfr[nt16 * 2 + 0][0] = r0; bfr[nt16 * 2 + 0][1] = r2;
                bfr[nt16 * 2 + 1][0] = r1; bfr[nt16 * 2 + 1][1] = r3;
            }
            #pragma unroll
            for (int mt = 0; mt < 4; mt++)
                #pragma unroll
                for (int nt = 0; nt < 4; nt++)
                    mma16816(acc[mt][nt], afr[mt], bfr[nt]);
        }
        __syncthreads();
    }

    // Epilogue: c0,c1 -> (row=gid, col=2*tig); c2,c3 -> (row=gid+8)
    const int gid = lane >> 2;
    const int tig = lane & 3;
    #pragma unroll
    for (int mt = 0; mt < 4; mt++) {
        #pragma unroll
        for (int nt = 0; nt < 4; nt++) {
            const int r = m0 + warp_m * 64 + mt * 16 + gid;
            const int c = n0 + warp_n * 32 + nt * 8 + 2 * tig;
            *(float2*)(Cout + (size_t)r * C_DIM + c) =
                make_float2(acc[mt][nt][0], acc[mt][nt][1]);
            *(float2*)(Cout + (size_t)(r + 8) * C_DIM + c) =
                make_float2(acc[mt][nt][2], acc[mt][nt][3]);
        }
    }
}

// ---------------------------------------------------------------------------
// Row softmax over C=512; write result to both soft and raw output regions.
// ---------------------------------------------------------------------------
__global__ void __launch_bounds__(128)
softmax_kernel(const float* __restrict__ cam, float* __restrict__ out)
{
    const int row  = blockIdx.x;
    const int tid  = threadIdx.x;
    const int lane = tid & 31;
    const int wid  = tid >> 5;

    const float4* rp = (const float4*)(cam + (size_t)row * C_DIM);
    float4 v = rp[tid];

    __shared__ float red[8];

    float m = fmaxf(fmaxf(v.x, v.y), fmaxf(v.z, v.w));
    #pragma unroll
    for (int o = 16; o > 0; o >>= 1)
        m = fmaxf(m, __shfl_xor_sync(0xFFFFFFFFu, m, o));
    if (lane == 0) red[wid] = m;
    __syncthreads();
    m = fmaxf(fmaxf(red[0], red[1]), fmaxf(red[2], red[3]));

    float e0 = expf(v.x - m), e1 = expf(v.y - m);
    float e2 = expf(v.z - m), e3 = expf(v.w - m);
    float s = (e0 + e1) + (e2 + e3);
    #pragma unroll
    for (int o = 16; o > 0; o >>= 1)
        s += __shfl_xor_sync(0xFFFFFFFFu, s, o);
    if (lane == 0) red[4 + wid] = s;
    __syncthreads();
    s = (red[4] + red[5]) + (red[6] + red[7]);

    float inv = 1.0f / s;
    float4 o4 = make_float4(e0 * inv, e1 * inv, e2 * inv, e3 * inv);

    ((float4*)(out + SOFT_OFF + (size_t)row * C_DIM))[tid] = o4;
    ((float4*)(out + RAW_OFF  + (size_t)row * C_DIM))[tid] = o4;
}

// ---------------------------------------------------------------------------
// logits[b][c] = dot(pooled[b], W[c]) / T + bias[c]; one warp per (b,c)
// ---------------------------------------------------------------------------
__global__ void __launch_bounds__(256)
logits_kernel(const float* __restrict__ W, const float* __restrict__ bias,
              float* __restrict__ out)
{
    const int b    = blockIdx.x;
    const int c    = blockIdx.y * 8 + (threadIdx.x >> 5);
    const int lane = threadIdx.x & 31;

    const float4* wp = (const float4*)(W + (size_t)c * D_DIM);
    const float4* pp = (const float4*)(g_pooled + b * D_DIM);

    float s = 0.0f;
    #pragma unroll
    for (int i = lane; i < D_DIM / 4; i += 32) {
        float4 w = wp[i];
        float4 p = pp[i];
        s += w.x * p.x + w.y * p.y + w.z * p.z + w.w * p.w;
    }
    #pragma unroll
    for (int o = 16; o > 0; o >>= 1)
        s += __shfl_xor_sync(0xFFFFFFFFu, s, o);

    if (lane == 0)
        out[LOGITS_OFF + (size_t)b * C_DIM + c] = s * (1.0f / T_DIM) + bias[c];
}

// ---------------------------------------------------------------------------
// loss = mean_b( -(logits[b][label_b] - logsumexp(logits[b])) )
// Labels arrive as int32 (JAX x64 disabled).
// ---------------------------------------------------------------------------
__global__ void __launch_bounds__(512)
loss_kernel(const float* __restrict__ out_logits,
            const int* __restrict__ labels, float* __restrict__ out)
{
    const int w    = threadIdx.x >> 5;
    const int lane = threadIdx.x & 31;
    const float* lp = out_logits + (size_t)w * C_DIM;

    float m = -3.4e38f;
    for (int i = lane; i < C_DIM; i += 32) m = fmaxf(m, lp[i]);
    #pragma unroll
    for (int o = 16; o > 0; o >>= 1)
        m = fmaxf(m, __shfl_xor_sync(0xFFFFFFFFu, m, o));

    float s = 0.0f;
    for (int i = lane; i < C_DIM; i += 32) s += expf(lp[i] - m);
    #pragma unroll
    for (int o = 16; o > 0; o >>= 1)
        s += __shfl_xor_sync(0xFFFFFFFFu, s, o);

    __shared__ float lb[16];
    if (lane == 0) {
        int lab = labels[w];
        lb[w] = -(lp[lab] - m - logf(s));
    }
    __syncthreads();
    if (threadIdx.x == 0) {
        float t = 0.0f;
        #pragma unroll
        for (int i = 0; i < 16; i++) t += lb[i];
        out[LOSS_OFF] = t * (1.0f / B_DIM);
    }
}

// ---------------------------------------------------------------------------
extern "C" void kernel_launch(void* const* d_in, const int* in_sizes, int n_in,
                              void* d_out, int out_size)
{
    const float* features = (const float*)d_in[0];
    const int*   labels   = (const int*)d_in[1];
    const float* W        = (const float*)d_in[2];
    const float* bias     = (const float*)d_in[3];
    float*       out      = (float*)d_out;

    float* cam_ptr;
    cudaGetSymbolAddress((void**)&cam_ptr, g_cam);
    __nv_bfloat16* abig_ptr;
    cudaGetSymbolAddress((void**)&abig_ptr, g_Abig);
    __nv_bfloat16* wbig_ptr;
    cudaGetSymbolAddress((void**)&wbig_ptr, g_Wbig);

    // 1) zero pooled sums, then fused bf16-split conversion + pooling
    zero_pooled_kernel<<<(B_DIM * D_DIM + 255) / 256, 256>>>();
    convert_pool_kernel<<<dim3(D_DIM / 256, TSPLIT, B_DIM), 256>>>(features);
    convert_w_kernel<<<(C_DIM * D_DIM) / 256, 256>>>(W);

    // 2) tensor-core CAM GEMM (bf16 3-term split, virtual K = 3072)
    cam_mma_kernel<<<dim3(C_DIM / 128, M_DIM / 128), 256>>>(abig_ptr, wbig_ptr, cam_ptr);

    // 3) softmax -> soft + raw output regions
    softmax_kernel<<<M_DIM, 128>>>(cam_ptr, out);

    // 4) logits
    logits_kernel<<<dim3(B_DIM, C_DIM / 8), 256>>>(W, bias, out);

    // 5) loss (reads logits region of d_out)
    loss_kernel<<<1, 512>>>(out + LOGITS_OFF, labels, out);
}

// round 8
// speedup vs baseline: 3.2592x; 1.4771x over previous
#include <cuda_runtime.h>
#include <cuda_fp16.h>
#include <cstdint>

// Problem dims (fixed per reference)
#define B_DIM 16
#define T_DIM 2048
#define D_DIM 1024
#define C_DIM 512
#define M_DIM (B_DIM * T_DIM)          // 32768 rows for CAM GEMM

// Output layout: [soft | raw | logits | loss]
#define SOFT_OFF   ((size_t)0)
#define RAW_OFF    ((size_t)M_DIM * C_DIM)
#define LOGITS_OFF ((size_t)2 * M_DIM * C_DIM)
#define LOSS_OFF   (LOGITS_OFF + (size_t)B_DIM * C_DIM)

// Scratch (static __device__, no allocation)
__device__ float  g_cam[(size_t)M_DIM * C_DIM];   // 64 MB
__device__ float  g_pooled[B_DIM * D_DIM];
__device__ __half g_Ah[(size_t)M_DIM * D_DIM];    // 64 MB fp16 features
__device__ __half g_Wh[(size_t)C_DIM * D_DIM];    // 1 MB fp16 weights

// ---------------------------------------------------------------------------
// PTX helpers
// ---------------------------------------------------------------------------
__device__ __forceinline__ void cpa16(uint32_t daddr, const void* gaddr) {
    asm volatile("cp.async.cg.shared.global [%0], [%1], 16;\n"
                 :: "r"(daddr), "l"(gaddr));
}
__device__ __forceinline__ void ldsm4(uint32_t& r0, uint32_t& r1,
                                      uint32_t& r2, uint32_t& r3, uint32_t addr) {
    asm volatile("ldmatrix.sync.aligned.m8n8.x4.shared.b16 {%0,%1,%2,%3}, [%4];"
                 : "=r"(r0), "=r"(r1), "=r"(r2), "=r"(r3) : "r"(addr));
}
__device__ __forceinline__ void mma16816(float* c, const uint32_t* a, const uint32_t* b) {
    asm volatile(
        "mma.sync.aligned.m16n8k16.row.col.f32.f16.f16.f32 "
        "{%0,%1,%2,%3}, {%4,%5,%6,%7}, {%8,%9}, {%0,%1,%2,%3};"
        : "+f"(c[0]), "+f"(c[1]), "+f"(c[2]), "+f"(c[3])
        : "r"(a[0]), "r"(a[1]), "r"(a[2]), "r"(a[3]), "r"(b[0]), "r"(b[1]));
}

// ---------------------------------------------------------------------------
// Fused conversion (fp32 -> fp16) + mean-pool partial sums.
// ---------------------------------------------------------------------------
#define TSPLIT 8
__global__ void __launch_bounds__(256)
convert_pool_kernel(const float* __restrict__ f)
{
    const int d  = blockIdx.x * 256 + threadIdx.x;
    const int b  = blockIdx.z;
    const int t0 = blockIdx.y * (T_DIM / TSPLIT);

    float s = 0.0f;
    #pragma unroll 4
    for (int t = 0; t < T_DIM / TSPLIT; t++) {
        const size_t row = (size_t)b * T_DIM + t0 + t;
        float v = f[row * D_DIM + d];
        s += v;
        g_Ah[row * D_DIM + d] = __float2half_rn(v);
    }
    atomicAdd(&g_pooled[b * D_DIM + d], s);
}

__global__ void __launch_bounds__(256)
convert_w_kernel(const float* __restrict__ W)
{
    const int i = blockIdx.x * 256 + threadIdx.x;   // < C*D
    g_Wh[i] = __float2half_rn(W[i]);
}

__global__ void zero_pooled_kernel()
{
    int i = blockIdx.x * blockDim.x + threadIdx.x;
    if (i < B_DIM * D_DIM) g_pooled[i] = 0.0f;
}

// ---------------------------------------------------------------------------
// Tensor-core CAM GEMM: cam[m][n] = sum_k Ah[m][k] * Wh[n][k]  (K = 1024)
// 128x128 CTA tile, BK=32, double-buffered cp.async, ldmatrix + fp16 HMMA,
// fp32 accumulate. Swizzle: 16B chunk c within 64B row at c ^ ((row>>1)&3).
// ---------------------------------------------------------------------------
#define STAGE_BYTES 8192                 // 128 rows * 64 B

__device__ __forceinline__ void gemm_issue_loads(
    const __half* __restrict__ A, const __half* __restrict__ Bw,
    int m0, int n0, int k0, uint32_t baseA, uint32_t baseB, int stage,
    int ldrow, int ldc)
{
    #pragma unroll
    for (int j = 0; j < 2; j++) {
        const int row = ldrow + j * 64;
        const int sw  = ldc ^ ((row >> 1) & 3);
        cpa16(baseA + stage * STAGE_BYTES + row * 64 + sw * 16,
              A + (size_t)(m0 + row) * D_DIM + k0 + ldc * 8);
        cpa16(baseB + stage * STAGE_BYTES + row * 64 + sw * 16,
              Bw + (size_t)(n0 + row) * D_DIM + k0 + ldc * 8);
    }
}

__global__ void __launch_bounds__(256, 2)
cam_mma_kernel(const __half* __restrict__ A,
               const __half* __restrict__ Bw,
               float* __restrict__ Cout)
{
    __shared__ __align__(16) unsigned char sA[2 * STAGE_BYTES];
    __shared__ __align__(16) unsigned char sB[2 * STAGE_BYTES];

    const int tid    = threadIdx.x;
    const int lane   = tid & 31;
    const int wid    = tid >> 5;
    const int warp_m = wid >> 2;       // 0..1
    const int warp_n = wid & 3;        // 0..3
    const int m0 = blockIdx.y * 128;
    const int n0 = blockIdx.x * 128;

    const uint32_t baseA = (uint32_t)__cvta_generic_to_shared(sA);
    const uint32_t baseB = (uint32_t)__cvta_generic_to_shared(sB);

    const int ldrow = tid >> 2;        // 0..63 (j adds 64)
    const int ldc   = tid & 3;         // 16B chunk in row

    float acc[4][4][4];
    #pragma unroll
    for (int mt = 0; mt < 4; mt++)
        #pragma unroll
        for (int nt = 0; nt < 4; nt++)
            #pragma unroll
            for (int r = 0; r < 4; r++)
                acc[mt][nt][r] = 0.0f;

    gemm_issue_loads(A, Bw, m0, n0, 0, baseA, baseB, 0, ldrow, ldc);
    asm volatile("cp.async.commit_group;\n");

    const int NITER = D_DIM / 32;      // 32
    for (int it = 0; it < NITER; it++) {
        if (it + 1 < NITER)
            gemm_issue_loads(A, Bw, m0, n0, (it + 1) * 32, baseA, baseB,
                             (it + 1) & 1, ldrow, ldc);
        asm volatile("cp.async.commit_group;\n");
        asm volatile("cp.async.wait_group 1;\n");
        __syncthreads();

        const int st = it & 1;
        #pragma unroll
        for (int ks = 0; ks < 2; ks++) {
            uint32_t afr[4][4];
            #pragma unroll
            for (int mt = 0; mt < 4; mt++) {
                const int row   = warp_m * 64 + mt * 16 + (lane & 15);
                const int chunk = (2 * ks + (lane >> 4)) ^ ((row >> 1) & 3);
                ldsm4(afr[mt][0], afr[mt][1], afr[mt][2], afr[mt][3],
                      baseA + st * STAGE_BYTES + row * 64 + chunk * 16);
            }
            uint32_t bfr[4][2];
            #pragma unroll
            for (int nt16 = 0; nt16 < 2; nt16++) {
                const int row   = warp_n * 32 + nt16 * 16 + (lane & 15);
                const int chunk = (2 * ks + (lane >> 4)) ^ ((row >> 1) & 3);
                uint32_t r0, r1, r2, r3;
                ldsm4(r0, r1, r2, r3,
                      baseB + st * STAGE_BYTES + row * 64 + chunk * 16);
                bfr[nt16 * 2 + 0][0] = r0; bfr[nt16 * 2 + 0][1] = r2;
                bfr[nt16 * 2 + 1][0] = r1; bfr[nt16 * 2 + 1][1] = r3;
            }
            #pragma unroll
            for (int mt = 0; mt < 4; mt++)
                #pragma unroll
                for (int nt = 0; nt < 4; nt++)
                    mma16816(acc[mt][nt], afr[mt], bfr[nt]);
        }
        __syncthreads();
    }

    // Epilogue: c0,c1 -> (row=gid, col=2*tig); c2,c3 -> (row=gid+8)
    const int gid = lane >> 2;
    const int tig = lane & 3;
    #pragma unroll
    for (int mt = 0; mt < 4; mt++) {
        #pragma unroll
        for (int nt = 0; nt < 4; nt++) {
            const int r = m0 + warp_m * 64 + mt * 16 + gid;
            const int c = n0 + warp_n * 32 + nt * 8 + 2 * tig;
            *(float2*)(Cout + (size_t)r * C_DIM + c) =
                make_float2(acc[mt][nt][0], acc[mt][nt][1]);
            *(float2*)(Cout + (size_t)(r + 8) * C_DIM + c) =
                make_float2(acc[mt][nt][2], acc[mt][nt][3]);
        }
    }
}

// ---------------------------------------------------------------------------
// Row softmax over C=512; write result to both soft and raw output regions.
// ---------------------------------------------------------------------------
__global__ void __launch_bounds__(128)
softmax_kernel(const float* __restrict__ cam, float* __restrict__ out)
{
    const int row  = blockIdx.x;
    const int tid  = threadIdx.x;
    const int lane = tid & 31;
    const int wid  = tid >> 5;

    const float4* rp = (const float4*)(cam + (size_t)row * C_DIM);
    float4 v = rp[tid];

    __shared__ float red[8];

    float m = fmaxf(fmaxf(v.x, v.y), fmaxf(v.z, v.w));
    #pragma unroll
    for (int o = 16; o > 0; o >>= 1)
        m = fmaxf(m, __shfl_xor_sync(0xFFFFFFFFu, m, o));
    if (lane == 0) red[wid] = m;
    __syncthreads();
    m = fmaxf(fmaxf(red[0], red[1]), fmaxf(red[2], red[3]));

    float e0 = expf(v.x - m), e1 = expf(v.y - m);
    float e2 = expf(v.z - m), e3 = expf(v.w - m);
    float s = (e0 + e1) + (e2 + e3);
    #pragma unroll
    for (int o = 16; o > 0; o >>= 1)
        s += __shfl_xor_sync(0xFFFFFFFFu, s, o);
    if (lane == 0) red[4 + wid] = s;
    __syncthreads();
    s = (red[4] + red[5]) + (red[6] + red[7]);

    float inv = 1.0f / s;
    float4 o4 = make_float4(e0 * inv, e1 * inv, e2 * inv, e3 * inv);

    ((float4*)(out + SOFT_OFF + (size_t)row * C_DIM))[tid] = o4;
    ((float4*)(out + RAW_OFF  + (size_t)row * C_DIM))[tid] = o4;
}

// ---------------------------------------------------------------------------
// logits[b][c] = dot(pooled[b], W[c]) / T + bias[c]; one warp per (b,c)
// ---------------------------------------------------------------------------
__global__ void __launch_bounds__(256)
logits_kernel(const float* __restrict__ W, const float* __restrict__ bias,
              float* __restrict__ out)
{
    const int b    = blockIdx.x;
    const int c    = blockIdx.y * 8 + (threadIdx.x >> 5);
    const int lane = threadIdx.x & 31;

    const float4* wp = (const float4*)(W + (size_t)c * D_DIM);
    const float4* pp = (const float4*)(g_pooled + b * D_DIM);

    float s = 0.0f;
    #pragma unroll
    for (int i = lane; i < D_DIM / 4; i += 32) {
        float4 w = wp[i];
        float4 p = pp[i];
        s += w.x * p.x + w.y * p.y + w.z * p.z + w.w * p.w;
    }
    #pragma unroll
    for (int o = 16; o > 0; o >>= 1)
        s += __shfl_xor_sync(0xFFFFFFFFu, s, o);

    if (lane == 0)
        out[LOGITS_OFF + (size_t)b * C_DIM + c] = s * (1.0f / T_DIM) + bias[c];
}

// ---------------------------------------------------------------------------
// loss = mean_b( -(logits[b][label_b] - logsumexp(logits[b])) )
// Labels arrive as int32 (JAX x64 disabled).
// ---------------------------------------------------------------------------
__global__ void __launch_bounds__(512)
loss_kernel(const float* __restrict__ out_logits,
            const int* __restrict__ labels, float* __restrict__ out)
{
    const int w    = threadIdx.x >> 5;
    const int lane = threadIdx.x & 31;
    const float* lp = out_logits + (size_t)w * C_DIM;

    float m = -3.4e38f;
    for (int i = lane; i < C_DIM; i += 32) m = fmaxf(m, lp[i]);
    #pragma unroll
    for (int o = 16; o > 0; o >>= 1)
        m = fmaxf(m, __shfl_xor_sync(0xFFFFFFFFu, m, o));

    float s = 0.0f;
    for (int i = lane; i < C_DIM; i += 32) s += expf(lp[i] - m);
    #pragma unroll
    for (int o = 16; o > 0; o >>= 1)
        s += __shfl_xor_sync(0xFFFFFFFFu, s, o);

    __shared__ float lb[16];
    if (lane == 0) {
        int lab = labels[w];
        lb[w] = -(lp[lab] - m - logf(s));
    }
    __syncthreads();
    if (threadIdx.x == 0) {
        float t = 0.0f;
        #pragma unroll
        for (int i = 0; i < 16; i++) t += lb[i];
        out[LOSS_OFF] = t * (1.0f / B_DIM);
    }
}

// ---------------------------------------------------------------------------
extern "C" void kernel_launch(void* const* d_in, const int* in_sizes, int n_in,
                              void* d_out, int out_size)
{
    const float* features = (const float*)d_in[0];
    const int*   labels   = (const int*)d_in[1];
    const float* W        = (const float*)d_in[2];
    const float* bias     = (const float*)d_in[3];
    float*       out      = (float*)d_out;

    float* cam_ptr;
    cudaGetSymbolAddress((void**)&cam_ptr, g_cam);
    __half* ah_ptr;
    cudaGetSymbolAddress((void**)&ah_ptr, g_Ah);
    __half* wh_ptr;
    cudaGetSymbolAddress((void**)&wh_ptr, g_Wh);

    // 1) zero pooled sums, then fused fp16 conversion + pooling
    zero_pooled_kernel<<<(B_DIM * D_DIM + 255) / 256, 256>>>();
    convert_pool_kernel<<<dim3(D_DIM / 256, TSPLIT, B_DIM), 256>>>(features);
    convert_w_kernel<<<(C_DIM * D_DIM) / 256, 256>>>(W);

    // 2) tensor-core CAM GEMM (fp16 single-phase, K = 1024)
    cam_mma_kernel<<<dim3(C_DIM / 128, M_DIM / 128), 256>>>(ah_ptr, wh_ptr, cam_ptr);

    // 3) softmax -> soft + raw output regions
    softmax_kernel<<<M_DIM, 128>>>(cam_ptr, out);

    // 4) logits
    logits_kernel<<<dim3(B_DIM, C_DIM / 8), 256>>>(W, bias, out);

    // 5) loss (reads logits region of d_out)
    loss_kernel<<<1, 512>>>(out + LOGITS_OFF, labels, out);
}

// round 9
// speedup vs baseline: 4.2426x; 1.3017x over previous
#include <cuda_runtime.h>
#include <cuda_fp16.h>
#include <cstdint>

// Problem dims (fixed per reference)
#define B_DIM 16
#define T_DIM 2048
#define D_DIM 1024
#define C_DIM 512
#define M_DIM (B_DIM * T_DIM)          // 32768 rows for CAM GEMM

// Output layout: [soft | raw | logits | loss]
#define SOFT_OFF   ((size_t)0)
#define RAW_OFF    ((size_t)M_DIM * C_DIM)
#define LOGITS_OFF ((size_t)2 * M_DIM * C_DIM)
#define LOSS_OFF   (LOGITS_OFF + (size_t)B_DIM * C_DIM)

// Scratch (static __device__, no allocation)
__device__ float  g_cam[(size_t)M_DIM * C_DIM];   // 64 MB
__device__ float  g_pooled[B_DIM * D_DIM];
__device__ __half g_Ah[(size_t)M_DIM * D_DIM];    // 64 MB fp16 features
__device__ __half g_Wh[(size_t)C_DIM * D_DIM];    // 1 MB fp16 weights

// ---------------------------------------------------------------------------
// PTX helpers
// ---------------------------------------------------------------------------
__device__ __forceinline__ void cpa16(uint32_t daddr, const void* gaddr) {
    asm volatile("cp.async.cg.shared.global [%0], [%1], 16;\n"
                 :: "r"(daddr), "l"(gaddr));
}
__device__ __forceinline__ void ldsm4(uint32_t& r0, uint32_t& r1,
                                      uint32_t& r2, uint32_t& r3, uint32_t addr) {
    asm volatile("ldmatrix.sync.aligned.m8n8.x4.shared.b16 {%0,%1,%2,%3}, [%4];"
                 : "=r"(r0), "=r"(r1), "=r"(r2), "=r"(r3) : "r"(addr));
}
__device__ __forceinline__ void mma16816(float* c, const uint32_t* a, const uint32_t* b) {
    asm volatile(
        "mma.sync.aligned.m16n8k16.row.col.f32.f16.f16.f32 "
        "{%0,%1,%2,%3}, {%4,%5,%6,%7}, {%8,%9}, {%0,%1,%2,%3};"
        : "+f"(c[0]), "+f"(c[1]), "+f"(c[2]), "+f"(c[3])
        : "r"(a[0]), "r"(a[1]), "r"(a[2]), "r"(a[3]), "r"(b[0]), "r"(b[1]));
}

// ---------------------------------------------------------------------------
// Fused conversion (fp32 -> fp16) + mean-pool partial sums.
// ---------------------------------------------------------------------------
#define TSPLIT 8
__global__ void __launch_bounds__(256)
convert_pool_kernel(const float* __restrict__ f)
{
    const int d  = blockIdx.x * 256 + threadIdx.x;
    const int b  = blockIdx.z;
    const int t0 = blockIdx.y * (T_DIM / TSPLIT);

    float s = 0.0f;
    #pragma unroll 4
    for (int t = 0; t < T_DIM / TSPLIT; t++) {
        const size_t row = (size_t)b * T_DIM + t0 + t;
        float v = f[row * D_DIM + d];
        s += v;
        g_Ah[row * D_DIM + d] = __float2half_rn(v);
    }
    atomicAdd(&g_pooled[b * D_DIM + d], s);
}

__global__ void __launch_bounds__(256)
convert_w_kernel(const float* __restrict__ W)
{
    const int i = blockIdx.x * 256 + threadIdx.x;   // < C*D
    g_Wh[i] = __float2half_rn(W[i]);
}

__global__ void zero_pooled_kernel()
{
    int i = blockIdx.x * blockDim.x + threadIdx.x;
    if (i < B_DIM * D_DIM) g_pooled[i] = 0.0f;
}

// ---------------------------------------------------------------------------
// Tensor-core CAM GEMM: cam[m][n] = sum_k Ah[m][k] * Wh[n][k]  (K = 1024)
// CTA tile 128(M) x 256(N), stage BK=64 (128B fp16 rows), double buffered.
// 8 warps as 2(M) x 4(N); warp tile 64x64 -> acc[4][8][4].
// SW128 swizzle: 16B chunk c of a 128B row stored at c ^ (row & 7).
// Dynamic SMEM: A 2x16KB + B 2x32KB = 96KB.
// ---------------------------------------------------------------------------
#define A_STAGE 16384                  // 128 rows * 128 B
#define B_STAGE 32768                  // 256 rows * 128 B
#define SMEM_GEMM (2 * A_STAGE + 2 * B_STAGE)   // 98304

__device__ __forceinline__ void gemm_issue_loads(
    const __half* __restrict__ A, const __half* __restrict__ Bw,
    int m0, int n0, int k0, uint32_t baseA, uint32_t baseB, int stage, int tid)
{
    const int c  = tid & 7;            // 16B chunk within 128B row
    const int r0 = tid >> 3;           // 0..31

    const uint32_t abase = baseA + stage * A_STAGE;
    #pragma unroll
    for (int p = 0; p < 4; p++) {      // 128 A rows
        const int row = r0 + p * 32;
        cpa16(abase + row * 128 + ((c ^ (row & 7)) * 16),
              A + (size_t)(m0 + row) * D_DIM + k0 + c * 8);
    }
    const uint32_t bbase = baseB + stage * B_STAGE;
    #pragma unroll
    for (int p = 0; p < 8; p++) {      // 256 B rows
        const int row = r0 + p * 32;
        cpa16(bbase + row * 128 + ((c ^ (row & 7)) * 16),
              Bw + (size_t)(n0 + row) * D_DIM + k0 + c * 8);
    }
}

__global__ void __launch_bounds__(256, 1)
cam_mma_kernel(const __half* __restrict__ A,
               const __half* __restrict__ Bw,
               float* __restrict__ Cout)
{
    extern __shared__ __align__(128) unsigned char smem[];
    const uint32_t baseA = (uint32_t)__cvta_generic_to_shared(smem);
    const uint32_t baseB = baseA + 2 * A_STAGE;

    const int tid    = threadIdx.x;
    const int lane   = tid & 31;
    const int wid    = tid >> 5;
    const int warp_m = wid >> 2;       // 0..1
    const int warp_n = wid & 3;        // 0..3
    const int m0 = blockIdx.y * 128;
    const int n0 = blockIdx.x * 256;

    float acc[4][8][4];
    #pragma unroll
    for (int mt = 0; mt < 4; mt++)
        #pragma unroll
        for (int nt = 0; nt < 8; nt++)
            #pragma unroll
            for (int r = 0; r < 4; r++)
                acc[mt][nt][r] = 0.0f;

    gemm_issue_loads(A, Bw, m0, n0, 0, baseA, baseB, 0, tid);
    asm volatile("cp.async.commit_group;\n");

    const int NITER = D_DIM / 64;      // 16
    for (int it = 0; it < NITER; it++) {
        if (it + 1 < NITER)
            gemm_issue_loads(A, Bw, m0, n0, (it + 1) * 64, baseA, baseB,
                             (it + 1) & 1, tid);
        asm volatile("cp.async.commit_group;\n");
        asm volatile("cp.async.wait_group 1;\n");
        __syncthreads();

        const int st = it & 1;
        #pragma unroll
        for (int ks = 0; ks < 4; ks++) {
            uint32_t afr[4][4];
            #pragma unroll
            for (int mt = 0; mt < 4; mt++) {
                const int row   = warp_m * 64 + mt * 16 + (lane & 15);
                const int chunk = (2 * ks + (lane >> 4)) ^ (row & 7);
                ldsm4(afr[mt][0], afr[mt][1], afr[mt][2], afr[mt][3],
                      baseA + st * A_STAGE + row * 128 + chunk * 16);
            }
            uint32_t bfr[8][2];
            #pragma unroll
            for (int nt16 = 0; nt16 < 4; nt16++) {
                const int row   = warp_n * 64 + nt16 * 16 + (lane & 15);
                const int chunk = (2 * ks + (lane >> 4)) ^ (row & 7);
                uint32_t r0, r1, r2, r3;
                ldsm4(r0, r1, r2, r3,
                      baseB + st * B_STAGE + row * 128 + chunk * 16);
                bfr[nt16 * 2 + 0][0] = r0; bfr[nt16 * 2 + 0][1] = r2;
                bfr[nt16 * 2 + 1][0] = r1; bfr[nt16 * 2 + 1][1] = r3;
            }
            #pragma unroll
            for (int mt = 0; mt < 4; mt++)
                #pragma unroll
                for (int nt = 0; nt < 8; nt++)
                    mma16816(acc[mt][nt], afr[mt], bfr[nt]);
        }
        __syncthreads();
    }

    // Epilogue: c0,c1 -> (row=gid, col=2*tig); c2,c3 -> (row=gid+8)
    const int gid = lane >> 2;
    const int tig = lane & 3;
    #pragma unroll
    for (int mt = 0; mt < 4; mt++) {
        #pragma unroll
        for (int nt = 0; nt < 8; nt++) {
            const int r = m0 + warp_m * 64 + mt * 16 + gid;
            const int c = n0 + warp_n * 64 + nt * 8 + 2 * tig;
            *(float2*)(Cout + (size_t)r * C_DIM + c) =
                make_float2(acc[mt][nt][0], acc[mt][nt][1]);
            *(float2*)(Cout + (size_t)(r + 8) * C_DIM + c) =
                make_float2(acc[mt][nt][2], acc[mt][nt][3]);
        }
    }
}

// ---------------------------------------------------------------------------
// Row softmax over C=512; write result to both soft and raw output regions.
// ---------------------------------------------------------------------------
__global__ void __launch_bounds__(128)
softmax_kernel(const float* __restrict__ cam, float* __restrict__ out)
{
    const int row  = blockIdx.x;
    const int tid  = threadIdx.x;
    const int lane = tid & 31;
    const int wid  = tid >> 5;

    const float4* rp = (const float4*)(cam + (size_t)row * C_DIM);
    float4 v = rp[tid];

    __shared__ float red[8];

    float m = fmaxf(fmaxf(v.x, v.y), fmaxf(v.z, v.w));
    #pragma unroll
    for (int o = 16; o > 0; o >>= 1)
        m = fmaxf(m, __shfl_xor_sync(0xFFFFFFFFu, m, o));
    if (lane == 0) red[wid] = m;
    __syncthreads();
    m = fmaxf(fmaxf(red[0], red[1]), fmaxf(red[2], red[3]));

    float e0 = expf(v.x - m), e1 = expf(v.y - m);
    float e2 = expf(v.z - m), e3 = expf(v.w - m);
    float s = (e0 + e1) + (e2 + e3);
    #pragma unroll
    for (int o = 16; o > 0; o >>= 1)
        s += __shfl_xor_sync(0xFFFFFFFFu, s, o);
    if (lane == 0) red[4 + wid] = s;
    __syncthreads();
    s = (red[4] + red[5]) + (red[6] + red[7]);

    float inv = 1.0f / s;
    float4 o4 = make_float4(e0 * inv, e1 * inv, e2 * inv, e3 * inv);

    ((float4*)(out + SOFT_OFF + (size_t)row * C_DIM))[tid] = o4;
    ((float4*)(out + RAW_OFF  + (size_t)row * C_DIM))[tid] = o4;
}

// ---------------------------------------------------------------------------
// logits[b][c] = dot(pooled[b], W[c]) / T + bias[c]; one warp per (b,c)
// ---------------------------------------------------------------------------
__global__ void __launch_bounds__(256)
logits_kernel(const float* __restrict__ W, const float* __restrict__ bias,
              float* __restrict__ out)
{
    const int b    = blockIdx.x;
    const int c    = blockIdx.y * 8 + (threadIdx.x >> 5);
    const int lane = threadIdx.x & 31;

    const float4* wp = (const float4*)(W + (size_t)c * D_DIM);
    const float4* pp = (const float4*)(g_pooled + b * D_DIM);

    float s = 0.0f;
    #pragma unroll
    for (int i = lane; i < D_DIM / 4; i += 32) {
        float4 w = wp[i];
        float4 p = pp[i];
        s += w.x * p.x + w.y * p.y + w.z * p.z + w.w * p.w;
    }
    #pragma unroll
    for (int o = 16; o > 0; o >>= 1)
        s += __shfl_xor_sync(0xFFFFFFFFu, s, o);

    if (lane == 0)
        out[LOGITS_OFF + (size_t)b * C_DIM + c] = s * (1.0f / T_DIM) + bias[c];
}

// ---------------------------------------------------------------------------
// loss = mean_b( -(logits[b][label_b] - logsumexp(logits[b])) )
// Labels arrive as int32 (JAX x64 disabled).
// ---------------------------------------------------------------------------
__global__ void __launch_bounds__(512)
loss_kernel(const float* __restrict__ out_logits,
            const int* __restrict__ labels, float* __restrict__ out)
{
    const int w    = threadIdx.x >> 5;
    const int lane = threadIdx.x & 31;
    const float* lp = out_logits + (size_t)w * C_DIM;

    float m = -3.4e38f;
    for (int i = lane; i < C_DIM; i += 32) m = fmaxf(m, lp[i]);
    #pragma unroll
    for (int o = 16; o > 0; o >>= 1)
        m = fmaxf(m, __shfl_xor_sync(0xFFFFFFFFu, m, o));

    float s = 0.0f;
    for (int i = lane; i < C_DIM; i += 32) s += expf(lp[i] - m);
    #pragma unroll
    for (int o = 16; o > 0; o >>= 1)
        s += __shfl_xor_sync(0xFFFFFFFFu, s, o);

    __shared__ float lb[16];
    if (lane == 0) {
        int lab = labels[w];
        lb[w] = -(lp[lab] - m - logf(s));
    }
    __syncthreads();
    if (threadIdx.x == 0) {
        float t = 0.0f;
        #pragma unroll
        for (int i = 0; i < 16; i++) t += lb[i];
        out[LOSS_OFF] = t * (1.0f / B_DIM);
    }
}

// ---------------------------------------------------------------------------
extern "C" void kernel_launch(void* const* d_in, const int* in_sizes, int n_in,
                              void* d_out, int out_size)
{
    const float* features = (const float*)d_in[0];
    const int*   labels   = (const int*)d_in[1];
    const float* W        = (const float*)d_in[2];
    const float* bias     = (const float*)d_in[3];
    float*       out      = (float*)d_out;

    float* cam_ptr;
    cudaGetSymbolAddress((void**)&cam_ptr, g_cam);
    __half* ah_ptr;
    cudaGetSymbolAddress((void**)&ah_ptr, g_Ah);
    __half* wh_ptr;
    cudaGetSymbolAddress((void**)&wh_ptr, g_Wh);

    cudaFuncSetAttribute(cam_mma_kernel,
                         cudaFuncAttributeMaxDynamicSharedMemorySize, SMEM_GEMM);

    // 1) zero pooled sums, then fused fp16 conversion + pooling
    zero_pooled_kernel<<<(B_DIM * D_DIM + 255) / 256, 256>>>();
    convert_pool_kernel<<<dim3(D_DIM / 256, TSPLIT, B_DIM), 256>>>(features);
    convert_w_kernel<<<(C_DIM * D_DIM) / 256, 256>>>(W);

    // 2) tensor-core CAM GEMM (fp16, K = 1024), 128x256 CTA tile
    cam_mma_kernel<<<dim3(C_DIM / 256, M_DIM / 128), 256, SMEM_GEMM>>>(
        ah_ptr, wh_ptr, cam_ptr);

    // 3) softmax -> soft + raw output regions
    softmax_kernel<<<M_DIM, 128>>>(cam_ptr, out);

    // 4) logits
    logits_kernel<<<dim3(B_DIM, C_DIM / 8), 256>>>(W, bias, out);

    // 5) loss (reads logits region of d_out)
    loss_kernel<<<1, 512>>>(out + LOGITS_OFF, labels, out);
}